// round 16
// baseline (speedup 1.0000x reference)
#include <cuda_runtime.h>

constexpr int T_LEN = 131072;
constexpr int NCHAN = 256;
constexpr float ISQ2 = 0.70710678118654752440f;

// Contract (R14/R15 evidence): d_in = x f32[2^25], h0o(5), h1o(7),
// h0a,h0b,h1a,h1b,g0a,g0b,g1a,g1b (10 each), f32, element counts, signature order.
// d_out = 33685504 f32: phi[262144] then psi0..7 REAL PARTS (complex cast to f32).

__device__ float g_F[96];   // 0:h0o(5) 8:h1o(7) 16:h0a 26:h0b 36:h1a 46:h1b 56:g0a 66:g0b 76:g1a 86:g1b

// Ping-pong deinterleaved chain scratch (a-tree = E, b-tree = O).
__device__ float g_EA[NCHAN * 65536];
__device__ float g_OA[NCHAN * 65536];
__device__ float g_EB[NCHAN * 32768];
__device__ float g_OB[NCHAN * 32768];

__global__ void k_copy_filt(const float* h0o, const float* h1o,
                            const float* f0, const float* f1, const float* f2,
                            const float* f3, const float* f4, const float* f5,
                            const float* f6, const float* f7)
{
    if (threadIdx.x != 0 || blockIdx.x != 0) return;
    for (int i = 0; i < 96; i++) g_F[i] = 0.f;
    for (int i = 0; i < 5; i++) g_F[i] = h0o[i];
    for (int i = 0; i < 7; i++) g_F[8 + i] = h1o[i];
    const float* fs[8] = {f0, f1, f2, f3, f4, f5, f6, f7};
    for (int j = 0; j < 8; j++)
        for (int i = 0; i < 10; i++) g_F[16 + 10 * j + i] = fs[j][i];
}

// Level-0 lowpass, deinterleaved: E[m]=phi0[2m], O[m]=phi0[2m+1],
// phi0[n] = sum_{k<5} x[n-2+k]*h0o[k]. Chain length 65536 per channel.
__global__ void k_lvl0_phi(const float* __restrict__ x)
{
    long long idx = (long long)blockIdx.x * blockDim.x + threadIdx.x;
    if (idx >= (long long)NCHAN * 65536) return;
    int bc = (int)(idx >> 16);
    int m  = (int)(idx & 65535);
    const float* xc = x + (long long)bc * T_LEN;
    float e = 0.f, o = 0.f;
#pragma unroll
    for (int k = 0; k < 5; k++) {
        int ge = 2 * m - 2 + k, go = 2 * m - 1 + k;
        float xe = ((unsigned)ge < (unsigned)T_LEN) ? xc[ge] : 0.f;
        float xo = ((unsigned)go < (unsigned)T_LEN) ? xc[go] : 0.f;
        e = fmaf(xe, g_F[k], e);
        o = fmaf(xo, g_F[k], o);
    }
    g_EA[idx] = e;
    g_OA[idx] = o;
}

// psi0.real = hi[2m], hi[t] = sum_{k<7} x[t-3+k]*h1o[k]. 65536 per channel.
__global__ void k_lvl0_psi(const float* __restrict__ x, float* __restrict__ out)
{
    long long idx = (long long)blockIdx.x * blockDim.x + threadIdx.x;
    if (idx >= (long long)NCHAN * 65536) return;
    int bc = (int)(idx >> 16);
    int m  = (int)(idx & 65535);
    const float* xc = x + (long long)bc * T_LEN;
    float a = 0.f;
#pragma unroll
    for (int k = 0; k < 7; k++) {
        int g = 2 * m - 3 + k;
        float xv = ((unsigned)g < (unsigned)T_LEN) ? xc[g] : 0.f;
        a = fmaf(xv, g_F[8 + k], a);
    }
    out[262144LL + idx] = a;   // psi0.real base + bc*65536 + m
}

// Levels 1..7: lo_a[m] = sum_{k<10} Ep[2m-5+k]*f0a[k] (stride 2, pad 5/4).
// psi_j.real = hi_a*ISQ2 (conj only flips imag; b-tree highpass not needed).
// mode 0: write chains. mode 1 (final): also write phi = interleave(lo_a, lo_b).
__global__ void k_level(int srcA, int in_len, long long pbase,
                        int fbase, int mode, float* __restrict__ out)
{
    const float* Ep = srcA ? g_EA : g_EB;
    const float* Op = srcA ? g_OA : g_OB;
    float*       Ec = srcA ? g_EB : g_EA;
    float*       Oc = srcA ? g_OB : g_OA;
    const int out_len = in_len >> 1;
    long long idx = (long long)blockIdx.x * blockDim.x + threadIdx.x;
    if (idx >= (long long)NCHAN * out_len) return;
    int bc = (int)(idx / out_len);
    int m  = (int)(idx - (long long)bc * out_len);
    const long long eb = (long long)bc * in_len;
    float la = 0.f, lb = 0.f, ha = 0.f;
#pragma unroll
    for (int k = 0; k < 10; k++) {
        int g = 2 * m - 5 + k;
        bool v = ((unsigned)g < (unsigned)in_len);
        float we = v ? Ep[eb + g] : 0.f;
        float wo = v ? Op[eb + g] : 0.f;
        la = fmaf(we, g_F[fbase + k],      la);
        lb = fmaf(wo, g_F[fbase + 10 + k], lb);
        ha = fmaf(we, g_F[fbase + 20 + k], ha);
    }
    // psi_j.real at pbase + bc*out_len + m
    out[pbase + (long long)bc * out_len + m] = ha * ISQ2;

    if (mode == 0) {
        Ec[(long long)bc * out_len + m] = la * ISQ2;
        Oc[(long long)bc * out_len + m] = lb * ISQ2;
    } else {
        // final phi: interleave(lo_a, lo_b) at f32 offset bc*1024 + 2m
        long long fi = (long long)bc * 1024 + 2LL * m;
        float2 fv; fv.x = la * ISQ2; fv.y = lb * ISQ2;
        reinterpret_cast<float2*>(out + fi)[0] = fv;
    }
}

extern "C" void kernel_launch(void* const* d_in, const int* in_sizes, int n_in,
                              void* d_out, int out_size)
{
    if (!d_in || !d_out || n_in < 11) return;
    const float* x   = (const float*)d_in[0];
    const float* h0o = (const float*)d_in[1];
    const float* h1o = (const float*)d_in[2];
    const float* h0a = (const float*)d_in[3];
    const float* h0b = (const float*)d_in[4];
    const float* h1a = (const float*)d_in[5];
    const float* h1b = (const float*)d_in[6];
    const float* g0a = (const float*)d_in[7];
    const float* g0b = (const float*)d_in[8];
    const float* g1a = (const float*)d_in[9];
    const float* g1b = (const float*)d_in[10];
    float* out = (float*)d_out;

    // psi_j REAL-part base offsets (f32): cumulative, phi first.
    // counts/ch: psi0 65536, then 32768,16384,8192,4096,2048,1024,512.
    const long long PSI_OFF[8] = {
        262144LL, 17039360LL, 25427968LL, 29622272LL,
        31719424LL, 32768000LL, 33292288LL, 33554432LL};
    // max write: 33554432 + 255*512 + 511 = 33685503 < out_size ✓ exact fit

    const int NT = 256;
    k_copy_filt<<<1, 1>>>(h0o, h1o, h0a, h0b, h1a, h1b, g0a, g0b, g1a, g1b);
    k_lvl0_phi<<<(int)(((long long)NCHAN * 65536 + NT - 1) / NT), NT>>>(x);
    k_lvl0_psi<<<(int)(((long long)NCHAN * 65536 + NT - 1) / NT), NT>>>(x, out);

    int in_len = 65536, srcA = 1;
    for (int j = 1; j <= 7; j++) {
        bool odd = (j & 1);
        int fbase = odd ? 56 : 16;         // g-set : h-set
        int mode = (j == 7) ? 1 : 0;
        int out_len = in_len >> 1;
        long long total = (long long)NCHAN * out_len;
        k_level<<<(int)((total + NT - 1) / NT), NT>>>(
            srcA, in_len, PSI_OFF[j], fbase, mode, out);
        in_len = out_len;
        srcA ^= 1;
    }
}

// round 17
// speedup vs baseline: 1.5244x; 1.5244x over previous
#include <cuda_runtime.h>

constexpr int T_LEN = 131072;
constexpr int NCHAN = 256;
constexpr float ISQ2 = 0.70710678118654752440f;

// Contract (R14-R16, verified passing): d_in = x f32[2^25], h0o(5), h1o(7),
// h0a,h0b,h1a,h1b,g0a,g0b,g1a,g1b (10 each), f32, signature order.
// d_out = 33685504 f32: phi[262144] then psi0..7 REAL PARTS.

__device__ float g_F[96];   // 0:h0o(5) 8:h1o(7) 16:h0a 26:h0b 36:h1a 46:h1b 56:g0a 66:g0b 76:g1a 86:g1b

// Ping-pong deinterleaved chain scratch (a-tree = E, b-tree = O).
__device__ float g_EA[NCHAN * 65536];
__device__ float g_OA[NCHAN * 65536];
__device__ float g_EB[NCHAN * 32768];
__device__ float g_OB[NCHAN * 32768];

__global__ void k_copy_filt(const float* h0o, const float* h1o,
                            const float* f0, const float* f1, const float* f2,
                            const float* f3, const float* f4, const float* f5,
                            const float* f6, const float* f7)
{
    if (threadIdx.x != 0 || blockIdx.x != 0) return;
    for (int i = 0; i < 96; i++) g_F[i] = 0.f;
    for (int i = 0; i < 5; i++) g_F[i] = h0o[i];
    for (int i = 0; i < 7; i++) g_F[8 + i] = h1o[i];
    const float* fs[8] = {f0, f1, f2, f3, f4, f5, f6, f7};
    for (int j = 0; j < 8; j++)
        for (int i = 0; i < 10; i++) g_F[16 + 10 * j + i] = fs[j][i];
}

// Fused level 0: one thread per m computes E=phi0[2m], O=phi0[2m+1],
// psi0.real[m]=hi[2m], all from one 8-float x window x[2m-4 .. 2m+3].
__global__ void k_lvl0(const float* __restrict__ x, float* __restrict__ out)
{
    long long idx = (long long)blockIdx.x * blockDim.x + threadIdx.x;
    if (idx >= (long long)NCHAN * 65536) return;
    int bc = (int)(idx >> 16);
    int m  = (int)(idx & 65535);
    const float* xc = x + (long long)bc * T_LEN;

    float w[8];                     // w[j] = x[2m-4+j]
    if (m >= 2 && m <= 65533) {
        const float2* x2 = (const float2*)xc;
        float2 p0 = x2[m - 2], p1 = x2[m - 1], p2 = x2[m], p3 = x2[m + 1];
        w[0] = p0.x; w[1] = p0.y; w[2] = p1.x; w[3] = p1.y;
        w[4] = p2.x; w[5] = p2.y; w[6] = p3.x; w[7] = p3.y;
    } else {
#pragma unroll
        for (int j = 0; j < 8; j++) {
            int g = 2 * m - 4 + j;
            w[j] = ((unsigned)g < (unsigned)T_LEN) ? xc[g] : 0.f;
        }
    }
    float psi = 0.f, e = 0.f, o = 0.f;
#pragma unroll
    for (int k = 0; k < 7; k++) psi = fmaf(w[k + 1], g_F[8 + k], psi);  // x[2m-3+k]
#pragma unroll
    for (int k = 0; k < 5; k++) {
        e = fmaf(w[k + 2], g_F[k], e);   // x[2m-2+k]
        o = fmaf(w[k + 3], g_F[k], o);   // x[2m-1+k]
    }
    g_EA[idx] = e;
    g_OA[idx] = o;
    out[262144LL + idx] = psi;
}

// Levels 1..7, TWO outputs (m2, m2+1) per thread sharing a 14-float window
// per tree: prev[2*m2-6 .. 2*m2+7]. psi_j.real = ha*ISQ2 only.
// mode 0: write chains (float2). mode 1 (final): write phi (float4 interleave).
__global__ void k_level2(int srcA, int in_len, long long pbase,
                         int fbase, int mode, float* __restrict__ out)
{
    const float* Ep = srcA ? g_EA : g_EB;
    const float* Op = srcA ? g_OA : g_OB;
    float*       Ec = srcA ? g_EB : g_EA;
    float*       Oc = srcA ? g_OB : g_OA;
    const int out_len = in_len >> 1;
    const int half    = out_len >> 1;        // threads per channel
    long long idx = (long long)blockIdx.x * blockDim.x + threadIdx.x;
    if (idx >= (long long)NCHAN * half) return;
    int bc = (int)(idx / half);
    int t  = (int)(idx - (long long)bc * half);
    int m2 = 2 * t;
    const long long eb = (long long)bc * in_len;

    float ew[14], ow[14];                    // prev[2*m2-6+j]
    if (t >= 2 && m2 <= (in_len >> 1) - 4) {
        const float2* E2 = (const float2*)(Ep + eb);
        const float2* O2 = (const float2*)(Op + eb);
        int b = m2 - 3;                      // float2 index of prev[2*m2-6]
#pragma unroll
        for (int j = 0; j < 7; j++) {
            float2 pe = E2[b + j], po = O2[b + j];
            ew[2 * j] = pe.x; ew[2 * j + 1] = pe.y;
            ow[2 * j] = po.x; ow[2 * j + 1] = po.y;
        }
    } else {
#pragma unroll
        for (int j = 0; j < 14; j++) {
            int g = 2 * m2 - 6 + j;
            bool v = ((unsigned)g < (unsigned)in_len);
            ew[j] = v ? Ep[eb + g] : 0.f;
            ow[j] = v ? Op[eb + g] : 0.f;
        }
    }

    float la0 = 0.f, lb0 = 0.f, ha0 = 0.f;
    float la1 = 0.f, lb1 = 0.f, ha1 = 0.f;
#pragma unroll
    for (int k = 0; k < 10; k++) {
        float f0a = g_F[fbase + k];
        float f0b = g_F[fbase + 10 + k];
        float f1a = g_F[fbase + 20 + k];
        // out m2:   taps prev[2*m2-5+k] = w[k+1]
        la0 = fmaf(ew[k + 1], f0a, la0);
        lb0 = fmaf(ow[k + 1], f0b, lb0);
        ha0 = fmaf(ew[k + 1], f1a, ha0);
        // out m2+1: taps prev[2*m2-3+k] = w[k+3]
        la1 = fmaf(ew[k + 3], f0a, la1);
        lb1 = fmaf(ow[k + 3], f0b, lb1);
        ha1 = fmaf(ew[k + 3], f1a, ha1);
    }

    // psi_j.real pair (aligned float2: pbase, bc*out_len, m2 all even)
    float2 pv; pv.x = ha0 * ISQ2; pv.y = ha1 * ISQ2;
    reinterpret_cast<float2*>(out + pbase + (long long)bc * out_len + m2)[0] = pv;

    if (mode == 0) {
        long long cb = (long long)bc * out_len + m2;
        float2 ev; ev.x = la0 * ISQ2; ev.y = la1 * ISQ2;
        float2 ov; ov.x = lb0 * ISQ2; ov.y = lb1 * ISQ2;
        reinterpret_cast<float2*>(Ec + cb)[0] = ev;
        reinterpret_cast<float2*>(Oc + cb)[0] = ov;
    } else {
        // final phi: interleave(lo_a, lo_b): 4 consecutive f32 at bc*1024 + 2*m2
        long long fi = (long long)bc * 1024 + 2LL * m2;    // multiple of 4
        float4 fv;
        fv.x = la0 * ISQ2; fv.y = lb0 * ISQ2;
        fv.z = la1 * ISQ2; fv.w = lb1 * ISQ2;
        reinterpret_cast<float4*>(out + fi)[0] = fv;
    }
}

extern "C" void kernel_launch(void* const* d_in, const int* in_sizes, int n_in,
                              void* d_out, int out_size)
{
    if (!d_in || !d_out || n_in < 11) return;
    const float* x   = (const float*)d_in[0];
    const float* h0o = (const float*)d_in[1];
    const float* h1o = (const float*)d_in[2];
    float* out = (float*)d_out;

    // psi_j REAL-part base offsets (f32), phi first.
    const long long PSI_OFF[8] = {
        262144LL, 17039360LL, 25427968LL, 29622272LL,
        31719424LL, 32768000LL, 33292288LL, 33554432LL};

    const int NT = 256;
    k_copy_filt<<<1, 1>>>(h0o, h1o,
                          (const float*)d_in[3], (const float*)d_in[4],
                          (const float*)d_in[5], (const float*)d_in[6],
                          (const float*)d_in[7], (const float*)d_in[8],
                          (const float*)d_in[9], (const float*)d_in[10]);

    k_lvl0<<<(int)(((long long)NCHAN * 65536 + NT - 1) / NT), NT>>>(x, out);

    int in_len = 65536, srcA = 1;
    for (int j = 1; j <= 7; j++) {
        bool odd = (j & 1);
        int fbase = odd ? 56 : 16;         // g-set : h-set
        int mode = (j == 7) ? 1 : 0;
        int half = in_len >> 2;            // threads per channel (out_len/2)
        long long total = (long long)NCHAN * half;
        k_level2<<<(int)((total + NT - 1) / NT), NT>>>(
            srcA, in_len, PSI_OFF[j], fbase, mode, out);
        in_len >>= 1;
        srcA ^= 1;
    }
}